// round 3
// baseline (speedup 1.0000x reference)
#include <cuda_runtime.h>
#include <cstdint>

// Problem shape (fixed)
#define Bn   16
#define Tn   8192
#define Cn   128
#define NCH  256
#define CT   32            // Tn / NCH
#define WPB  2             // chunks (warps) per block
#define FULLMASK 0xFFFFFFFFu

// ---------------- device scratch (static; no allocations) ----------------
__device__ float g_p1loc[Bn * NCH * Cn * 2];  // per-chunk local (Sx,Sn) interleaved per channel
__device__ float g_p1inc[Bn * NCH * Cn * 2];  // per-chunk inclusive (Sx,Sn)
__device__ float g_p2loc[Bn * NCH * Cn];      // per-chunk local  Ssq
__device__ float g_p2inc[Bn * NCH * Cn];      // per-chunk inclusive Ssq
__device__ unsigned g_flag1[Bn * NCH];        // 0=none 1=local 2=inclusive
__device__ unsigned g_flag2[Bn * NCH];

// ---------------- helpers ----------------
__device__ __forceinline__ unsigned ld_acquire(const unsigned* p) {
    unsigned v;
    asm volatile("ld.acquire.gpu.u32 %0, [%1];" : "=r"(v) : "l"(p) : "memory");
    return v;
}
__device__ __forceinline__ void st_release(unsigned* p, unsigned v) {
    asm volatile("st.release.gpu.u32 [%0], %1;" :: "l"(p), "r"(v) : "memory");
}
__device__ __forceinline__ float frcp(float x) {
    float r; asm("rcp.approx.ftz.f32 %0, %1;" : "=f"(r) : "f"(x)); return r;
}
__device__ __forceinline__ float frsq(float x) {
    float r; asm("rsqrt.approx.ftz.f32 %0, %1;" : "=f"(r) : "f"(x)); return r;
}
__device__ __forceinline__ float4 ldcg4(const float4* p) { return __ldcg(p); }

__global__ void revin_init_flags() {
    int i = blockIdx.x * blockDim.x + threadIdx.x;
    if (i < Bn * NCH) { g_flag1[i] = 0u; g_flag2[i] = 0u; }
}

// ---------------- main kernel ----------------
// grid = (NCH/WPB, Bn), block = WPB warps. warp <-> chunk; lane owns channels 4l..4l+3.
__global__ __launch_bounds__(WPB * 32) void revin_kernel(
    const float* __restrict__ x,
    const float* __restrict__ mask,
    float* __restrict__ out)
{
    __shared__ float4 xs[WPB][CT][32];

    const int w = threadIdx.x >> 5;
    const int l = threadIdx.x & 31;
    const int k = blockIdx.x * WPB + w;      // chunk index along T
    const int b = blockIdx.y;                // batch
    const int bN = b * NCH;

    const size_t base = (size_t)(b * Tn + k * CT) * Cn + 4 * l;
    const float4* __restrict__ px = (const float4*)(x + base);
    const float4* __restrict__ pm = (const float4*)(mask + base);
    float4* __restrict__ po = (float4*)(out + base);
    // t stride in float4s = Cn/4 = 32

    // ---------------- Phase 1: one gmem pass; cache x in smem, mask as bits ----
    float4 lx = make_float4(0.f, 0.f, 0.f, 0.f);
    float4 ln = make_float4(0.f, 0.f, 0.f, 0.f);
    unsigned m0 = 0, m1 = 0, m2 = 0, m3 = 0;   // nm bits (1 = observed) per channel
    #pragma unroll
    for (int t = 0; t < CT; ++t) {
        float4 xv = px[t * 32];
        float4 mv = pm[t * 32];
        xs[w][t][l] = xv;
        lx.x += xv.x; lx.y += xv.y; lx.z += xv.z; lx.w += xv.w;
        unsigned b0 = (mv.x == 0.f), b1 = (mv.y == 0.f), b2 = (mv.z == 0.f), b3 = (mv.w == 0.f);
        ln.x += b0 ? 1.f : 0.f; ln.y += b1 ? 1.f : 0.f;
        ln.z += b2 ? 1.f : 0.f; ln.w += b3 ? 1.f : 0.f;
        m0 |= b0 << t; m1 |= b1 << t; m2 |= b2 << t; m3 |= b3 << t;
    }

    // publish local (Sx,Sn)
    {
        float* p = g_p1loc + ((size_t)(bN + k) * Cn + 4 * l) * 2;
        ((float4*)p)[0] = make_float4(lx.x, ln.x, lx.y, ln.y);
        ((float4*)p)[1] = make_float4(lx.z, ln.z, lx.w, ln.w);
        __syncwarp();
        __threadfence();
        if (l == 0) st_release(&g_flag1[bN + k], 1u);
    }

    // ---------------- Lookback 1 (windowed hybrid) ----------------
    float4 ex_x = make_float4(0.f, 0.f, 0.f, 0.f);
    float4 ex_n = make_float4(0.f, 0.f, 0.f, 0.f);
    if (k > 0) {
        int jhi = k - 1;
        for (;;) {
            int j = jhi - l;
            unsigned f = 0u;
            if (j >= 0) {
                f = ld_acquire(&g_flag1[bN + j]);
                while (f == 0u) { __nanosleep(30); f = ld_acquire(&g_flag1[bN + j]); }
            }
            int nvalid = (jhi + 1 < 32) ? (jhi + 1) : 32;
            unsigned ball2 = __ballot_sync(FULLMASK, (j >= 0) && (f == 2u));
            int L = ball2 ? (__ffs(ball2) - 1) : 32;
            int nsum = (L < nvalid) ? L : nvalid;
            #pragma unroll 4
            for (int jj = 0; jj < nsum; ++jj) {
                const float* p = g_p1loc + ((size_t)(bN + jhi - jj) * Cn + 4 * l) * 2;
                float4 a0 = ldcg4((const float4*)p);
                float4 a1 = ldcg4((const float4*)p + 1);
                ex_x.x += a0.x; ex_n.x += a0.y; ex_x.y += a0.z; ex_n.y += a0.w;
                ex_x.z += a1.x; ex_n.z += a1.y; ex_x.w += a1.z; ex_n.w += a1.w;
            }
            if (L < nvalid) {
                const float* p = g_p1inc + ((size_t)(bN + jhi - L) * Cn + 4 * l) * 2;
                float4 a0 = ldcg4((const float4*)p);
                float4 a1 = ldcg4((const float4*)p + 1);
                ex_x.x += a0.x; ex_n.x += a0.y; ex_x.y += a0.z; ex_n.y += a0.w;
                ex_x.z += a1.x; ex_n.z += a1.y; ex_x.w += a1.z; ex_n.w += a1.w;
                break;
            }
            jhi -= nvalid;
            if (jhi < 0) break;
        }
    }
    // publish inclusive (Sx,Sn)
    {
        float* p = g_p1inc + ((size_t)(bN + k) * Cn + 4 * l) * 2;
        ((float4*)p)[0] = make_float4(ex_x.x + lx.x, ex_n.x + ln.x, ex_x.y + lx.y, ex_n.y + ln.y);
        ((float4*)p)[1] = make_float4(ex_x.z + lx.z, ex_n.z + ln.z, ex_x.w + lx.w, ex_n.w + ln.w);
        __syncwarp();
        __threadfence();
        if (l == 0) st_release(&g_flag1[bN + k], 2u);
    }

    // ---------------- Phase 2: running mean; local Ssq; store (x-mean) back ----
    float4 sx = ex_x, sn = ex_n;
    float4 lsq = make_float4(0.f, 0.f, 0.f, 0.f);
    #pragma unroll
    for (int t = 0; t < CT; ++t) {
        float4 xv = xs[w][t][l];
        float nmf, nn, mean, val, d;

        nmf = ((m0 >> t) & 1u) ? 1.f : 0.f;
        sx.x += xv.x; sn.x += nmf;
        nn = (sn.x == 0.f) ? 1.f : sn.x;
        mean = sx.x * frcp(nn);
        val = xv.x - mean; d = val * nmf; lsq.x = fmaf(d, d, lsq.x); xv.x = val;

        nmf = ((m1 >> t) & 1u) ? 1.f : 0.f;
        sx.y += xv.y; sn.y += nmf;
        nn = (sn.y == 0.f) ? 1.f : sn.y;
        mean = sx.y * frcp(nn);
        val = xv.y - mean; d = val * nmf; lsq.y = fmaf(d, d, lsq.y); xv.y = val;

        nmf = ((m2 >> t) & 1u) ? 1.f : 0.f;
        sx.z += xv.z; sn.z += nmf;
        nn = (sn.z == 0.f) ? 1.f : sn.z;
        mean = sx.z * frcp(nn);
        val = xv.z - mean; d = val * nmf; lsq.z = fmaf(d, d, lsq.z); xv.z = val;

        nmf = ((m3 >> t) & 1u) ? 1.f : 0.f;
        sx.w += xv.w; sn.w += nmf;
        nn = (sn.w == 0.f) ? 1.f : sn.w;
        mean = sx.w * frcp(nn);
        val = xv.w - mean; d = val * nmf; lsq.w = fmaf(d, d, lsq.w); xv.w = val;

        xs[w][t][l] = xv;   // now holds (x - mean_t)
    }

    // publish local Ssq
    {
        float* p = g_p2loc + (size_t)(bN + k) * Cn + 4 * l;
        *((float4*)p) = lsq;
        __syncwarp();
        __threadfence();
        if (l == 0) st_release(&g_flag2[bN + k], 1u);
    }

    // ---------------- Lookback 2 ----------------
    float4 ex_q = make_float4(0.f, 0.f, 0.f, 0.f);
    if (k > 0) {
        int jhi = k - 1;
        for (;;) {
            int j = jhi - l;
            unsigned f = 0u;
            if (j >= 0) {
                f = ld_acquire(&g_flag2[bN + j]);
                while (f == 0u) { __nanosleep(30); f = ld_acquire(&g_flag2[bN + j]); }
            }
            int nvalid = (jhi + 1 < 32) ? (jhi + 1) : 32;
            unsigned ball2 = __ballot_sync(FULLMASK, (j >= 0) && (f == 2u));
            int L = ball2 ? (__ffs(ball2) - 1) : 32;
            int nsum = (L < nvalid) ? L : nvalid;
            #pragma unroll 4
            for (int jj = 0; jj < nsum; ++jj) {
                const float* p = g_p2loc + (size_t)(bN + jhi - jj) * Cn + 4 * l;
                float4 a = ldcg4((const float4*)p);
                ex_q.x += a.x; ex_q.y += a.y; ex_q.z += a.z; ex_q.w += a.w;
            }
            if (L < nvalid) {
                const float* p = g_p2inc + (size_t)(bN + jhi - L) * Cn + 4 * l;
                float4 a = ldcg4((const float4*)p);
                ex_q.x += a.x; ex_q.y += a.y; ex_q.z += a.z; ex_q.w += a.w;
                break;
            }
            jhi -= nvalid;
            if (jhi < 0) break;
        }
    }
    // publish inclusive Ssq
    {
        float* p = g_p2inc + (size_t)(bN + k) * Cn + 4 * l;
        *((float4*)p) = make_float4(ex_q.x + lsq.x, ex_q.y + lsq.y, ex_q.z + lsq.z, ex_q.w + lsq.w);
        __syncwarp();
        __threadfence();
        if (l == 0) st_release(&g_flag2[bN + k], 2u);
    }

    // ---------------- Phase 3: output ----------------
    float4 sn2 = ex_n;
    float4 ssq = ex_q;
    #pragma unroll
    for (int t = 0; t < CT; ++t) {
        float4 val = xs[w][t][l];
        float4 o;
        float nmf, nn, d, var, inv, ov;

        nmf = ((m0 >> t) & 1u) ? 1.f : 0.f;
        sn2.x += nmf;
        nn = (sn2.x == 0.f) ? 1.f : sn2.x;
        d = val.x * nmf; ssq.x = fmaf(d, d, ssq.x);
        var = ssq.x * frcp(nn);
        inv = (var > 1e-10f) ? frsq(var) : 1.f;
        ov = val.x * inv; o.x = fminf(fmaxf(ov, -100.f), 100.f);

        nmf = ((m1 >> t) & 1u) ? 1.f : 0.f;
        sn2.y += nmf;
        nn = (sn2.y == 0.f) ? 1.f : sn2.y;
        d = val.y * nmf; ssq.y = fmaf(d, d, ssq.y);
        var = ssq.y * frcp(nn);
        inv = (var > 1e-10f) ? frsq(var) : 1.f;
        ov = val.y * inv; o.y = fminf(fmaxf(ov, -100.f), 100.f);

        nmf = ((m2 >> t) & 1u) ? 1.f : 0.f;
        sn2.z += nmf;
        nn = (sn2.z == 0.f) ? 1.f : sn2.z;
        d = val.z * nmf; ssq.z = fmaf(d, d, ssq.z);
        var = ssq.z * frcp(nn);
        inv = (var > 1e-10f) ? frsq(var) : 1.f;
        ov = val.z * inv; o.z = fminf(fmaxf(ov, -100.f), 100.f);

        nmf = ((m3 >> t) & 1u) ? 1.f : 0.f;
        sn2.w += nmf;
        nn = (sn2.w == 0.f) ? 1.f : sn2.w;
        d = val.w * nmf; ssq.w = fmaf(d, d, ssq.w);
        var = ssq.w * frcp(nn);
        inv = (var > 1e-10f) ? frsq(var) : 1.f;
        ov = val.w * inv; o.w = fminf(fmaxf(ov, -100.f), 100.f);

        po[t * 32] = o;
    }
}

// ---------------- launch ----------------
extern "C" void kernel_launch(void* const* d_in, const int* in_sizes, int n_in,
                              void* d_out, int out_size)
{
    const float* x    = (const float*)d_in[0];
    const float* mask = (const float*)d_in[1];
    float* out        = (float*)d_out;

    revin_init_flags<<<(Bn * NCH + 511) / 512, 512>>>();
    dim3 grid(NCH / WPB, Bn);
    revin_kernel<<<grid, WPB * 32>>>(x, mask, out);
}

// round 4
// speedup vs baseline: 1.5992x; 1.5992x over previous
#include <cuda_runtime.h>
#include <cstdint>

// Problem shape (fixed by the dataset)
#define Bn   16
#define Tn   8192
#define Cn   128
#define NCH  128
#define CT   (Tn / NCH)   // 64 timesteps per chunk

// ---------------- device scratch (no allocations allowed) ----------------
__device__ float g_aggx [Bn * NCH * Cn];   // per-chunk local sum of x
__device__ float g_aggn [Bn * NCH * Cn];   // per-chunk local sum of (1-mask)
__device__ float g_aggsq[Bn * NCH * Cn];   // per-chunk local sum of term^2
__device__ unsigned int g_flags[2 * Bn * NCH]; // phase1 flags, phase2 flags

// ---------------- small helpers ----------------
__device__ __forceinline__ unsigned int ld_acquire(const unsigned int* p) {
    unsigned int v;
    asm volatile("ld.acquire.gpu.u32 %0, [%1];" : "=r"(v) : "l"(p) : "memory");
    return v;
}
__device__ __forceinline__ void st_release(unsigned int* p, unsigned int v) {
    asm volatile("st.release.gpu.u32 [%0], %1;" :: "l"(p), "r"(v) : "memory");
}
__device__ __forceinline__ float frcp(float x) {
    float r; asm("rcp.approx.ftz.f32 %0, %1;" : "=f"(r) : "f"(x)); return r;
}
__device__ __forceinline__ float frsq(float x) {
    float r; asm("rsqrt.approx.ftz.f32 %0, %1;" : "=f"(r) : "f"(x)); return r;
}

// Zero the flags before every launch (graph replays included).
__global__ void revin_init_flags() {
    int i = blockIdx.x * blockDim.x + threadIdx.x;
    if (i < 2 * Bn * NCH) g_flags[i] = 0u;
}

// ---------------- main kernel ----------------
// grid = (NCH, Bn), block = 128 threads (thread = channel c)
__global__ __launch_bounds__(128) void revin_kernel(
    const float* __restrict__ x,
    const float* __restrict__ mask,
    float* __restrict__ out)
{
    const int k = blockIdx.x;          // chunk index along T
    const int b = blockIdx.y;          // batch
    const int c = threadIdx.x;         // channel

    const int base = (b * Tn + k * CT) * Cn + c;
    const float* __restrict__ px = x    + base;
    const float* __restrict__ pm = mask + base;
    float*       __restrict__ po = out  + base;

    const int aggBase = (b * NCH + k) * Cn + c;
    unsigned int* flagsA = &g_flags[b * NCH];            // phase-1 flags for this batch
    unsigned int* flagsB = &g_flags[Bn * NCH + b * NCH]; // phase-2 flags for this batch

    // ---------------- Phase 1: local sum of x; mask -> bits ----------------
    float Lx = 0.f;
    unsigned mb0 = 0u, mb1 = 0u;   // bit t set => observed (nm==1) at timestep t
    #pragma unroll 8
    for (int t = 0; t < CT; ++t) {
        float xv = px[t * Cn];
        float mv = pm[t * Cn];
        Lx += xv;
        unsigned obs = (mv == 0.f) ? 1u : 0u;
        if (t < 32) mb0 |= obs << t;
        else        mb1 |= obs << (t - 32);
    }
    float Ln = (float)(__popc(mb0) + __popc(mb1));

    g_aggx[aggBase] = Lx;
    g_aggn[aggBase] = Ln;
    __syncthreads();
    if (threadIdx.x == 0) {
        __threadfence();
        st_release(&flagsA[k], 1u);
    }

    // Lookback: wait for all predecessors' LOCAL aggregates (no serial chain).
    if (c < k) {
        while (ld_acquire(&flagsA[c]) == 0u) __nanosleep(40);
    }
    __syncthreads();

    float ex_x = 0.f, ex_n = 0.f;
    {
        const int rowBase = b * NCH * Cn + c;
        #pragma unroll 4
        for (int j = 0; j < k; ++j) {
            ex_x += g_aggx[rowBase + j * Cn];
            ex_n += g_aggn[rowBase + j * Cn];
        }
    }

    // ---------------- Phase 2: local sum of term^2 with true running mean ----
    float sx = ex_x, sn = ex_n, Lsq = 0.f;
    #pragma unroll 8
    for (int t = 0; t < CT; ++t) {
        float xv = px[t * Cn];
        unsigned obs = (t < 32) ? ((mb0 >> t) & 1u) : ((mb1 >> (t - 32)) & 1u);
        float nm = (float)obs;
        sx += xv;
        sn += nm;
        float nn   = (sn == 0.f) ? 1.f : sn;
        float mean = sx * frcp(nn);
        float d    = (xv - mean) * nm;
        Lsq        = fmaf(d, d, Lsq);
    }
    g_aggsq[aggBase] = Lsq;
    __syncthreads();
    if (threadIdx.x == 0) {
        __threadfence();
        st_release(&flagsB[k], 1u);
    }

    if (c < k) {
        while (ld_acquire(&flagsB[c]) == 0u) __nanosleep(40);
    }
    __syncthreads();

    float ex_sq = 0.f;
    {
        const int rowBase = b * NCH * Cn + c;
        #pragma unroll 4
        for (int j = 0; j < k; ++j) ex_sq += g_aggsq[rowBase + j * Cn];
    }

    // ---------------- Phase 3: produce output ----------------
    sx = ex_x; sn = ex_n;
    float ssq = ex_sq;
    #pragma unroll 8
    for (int t = 0; t < CT; ++t) {
        float xv = px[t * Cn];
        unsigned obs = (t < 32) ? ((mb0 >> t) & 1u) : ((mb1 >> (t - 32)) & 1u);
        float nm = (float)obs;
        sx += xv;
        sn += nm;
        float nn   = (sn == 0.f) ? 1.f : sn;
        float rcpn = frcp(nn);
        float mean = sx * rcpn;
        float d    = (xv - mean) * nm;
        ssq        = fmaf(d, d, ssq);
        float var  = ssq * rcpn;                       // std^2
        float inv  = (var > 1e-10f) ? frsq(var) : 1.f; // std > 1e-5 <=> var > 1e-10
        float o    = (xv - mean) * inv;
        o = fminf(fmaxf(o, -100.f), 100.f);
        po[t * Cn] = o;
    }
}

// ---------------- launch ----------------
extern "C" void kernel_launch(void* const* d_in, const int* in_sizes, int n_in,
                              void* d_out, int out_size)
{
    const float* x    = (const float*)d_in[0];
    const float* mask = (const float*)d_in[1];
    float* out        = (float*)d_out;

    revin_init_flags<<<(2 * Bn * NCH + 511) / 512, 512>>>();
    dim3 grid(NCH, Bn);
    revin_kernel<<<grid, 128>>>(x, mask, out);
}